// round 4
// baseline (speedup 1.0000x reference)
#include <cuda_runtime.h>
#include <cstdint>

#define N_NODES 50000
#define E_EDGES 800000
#define D_IN    256
#define D_H     256
#define R_REL   8
#define B_BAS   4

// ------------------------------------------------------------------
// Scratch (device globals; no runtime allocation allowed).
// Referenced ONLY from device code.
// ------------------------------------------------------------------
__device__ __align__(16) float g_xb[(size_t)N_NODES * (B_BAS * D_H)];   // 204.8 MB
__device__ __align__(16) float g_z [(size_t)N_NODES * (R_REL * D_H)];   // 409.6 MB
__device__ __align__(16) float g_h [(size_t)N_NODES * D_H];             // 51.2 MB
__device__ __align__(16) float g_w [D_IN * B_BAS * D_H];                // 1 MB
__device__ __align__(16) float g_norm[N_NODES * R_REL];
__device__ __align__(16) int   g_cnt [N_NODES * R_REL];

// ------------------------------------------------------------------
// Edge-count / norm   (edge arrays are INT32 — JAX x64 is disabled)
// ------------------------------------------------------------------
__global__ void zero_cnt_k() {
    int i = blockIdx.x * blockDim.x + threadIdx.x;
    if (i < N_NODES * R_REL) g_cnt[i] = 0;
}

__global__ void count_k(const int* __restrict__ ei,
                        const int* __restrict__ et) {
    int e = blockIdx.x * blockDim.x + threadIdx.x;
    if (e >= E_EDGES) return;
    int dst = ei[E_EDGES + e];
    int r   = et[e];
    atomicAdd(&g_cnt[dst * R_REL + r], 1);
}

__global__ void norm_k() {
    int i = blockIdx.x * blockDim.x + threadIdx.x;
    if (i >= N_NODES * R_REL) return;
    int c = g_cnt[i];
    g_norm[i] = 1.0f / (float)(c > 0 ? c : 1);
}

// ------------------------------------------------------------------
// basis [B, DIN, DH] -> g_w [DIN, B*DH]
// ------------------------------------------------------------------
__global__ void trans_basis_k(const float* __restrict__ basis) {
    int idx = blockIdx.x * blockDim.x + threadIdx.x;   // over DIN*B*DH
    if (idx >= D_IN * B_BAS * D_H) return;
    int o = idx & (D_H - 1);
    int b = (idx >> 8) & (B_BAS - 1);
    int i = idx >> 10;
    g_w[idx] = basis[(size_t)b * D_IN * D_H + (size_t)i * D_H + o];
}

// ------------------------------------------------------------------
// SGEMM: C[M,N] = A[M,256] * B[256,N] (+ bias). 128x128x8, 8x8/thread.
// aSel: 0 = Aext, 1 = g_h ; bSel: 0 = Bext, 1 = g_w
// cSel: 0 = Cext, 1 = g_xb, 2 = g_h
// ------------------------------------------------------------------
__global__ __launch_bounds__(256, 1)
void sgemm128_k(const float* __restrict__ Aext, int aSel,
                const float* __restrict__ Bext, int bSel,
                float* __restrict__ Cext, int cSel,
                int M, int N, const float* __restrict__ bias) {
    const int K = 256;
    __shared__ float As[8][128];
    __shared__ float Bs[8][128];

    const float* A  = aSel ? (const float*)g_h : Aext;
    const float* Bm = bSel ? (const float*)g_w : Bext;
    float* C = (cSel == 0) ? Cext : (cSel == 1 ? (float*)g_xb : (float*)g_h);

    int tid  = threadIdx.x;
    int row0 = blockIdx.y * 128;
    int col0 = blockIdx.x * 128;
    int tr = (tid >> 4) << 3;     // 0..120
    int tc = (tid & 15) << 3;     // 0..120

    float acc[8][8];
#pragma unroll
    for (int i = 0; i < 8; i++)
#pragma unroll
        for (int j = 0; j < 8; j++) acc[i][j] = 0.0f;

    int aRow = tid >> 1;            // 0..127
    int aCol = (tid & 1) << 2;      // 0 or 4
    int bRow = tid >> 5;            // 0..7
    int bCol = (tid & 31) << 2;     // 0..124

    const bool aValid = (row0 + aRow) < M;
    const float* Aptr = A + (size_t)(row0 + aRow) * K + aCol;
    const float* Bptr = Bm + (size_t)bRow * N + col0 + bCol;

    for (int k0 = 0; k0 < K; k0 += 8) {
        float4 av = aValid ? *(const float4*)(Aptr + k0)
                           : make_float4(0.f, 0.f, 0.f, 0.f);
        As[aCol + 0][aRow] = av.x;
        As[aCol + 1][aRow] = av.y;
        As[aCol + 2][aRow] = av.z;
        As[aCol + 3][aRow] = av.w;
        float4 bv = *(const float4*)(Bptr + (size_t)k0 * N);
        *(float4*)&Bs[bRow][bCol] = bv;
        __syncthreads();

#pragma unroll
        for (int k = 0; k < 8; ++k) {
            float ar[8], br[8];
#pragma unroll
            for (int i = 0; i < 8; i++) ar[i] = As[k][tr + i];
#pragma unroll
            for (int j = 0; j < 8; j++) br[j] = Bs[k][tc + j];
#pragma unroll
            for (int i = 0; i < 8; i++)
#pragma unroll
                for (int j = 0; j < 8; j++)
                    acc[i][j] = fmaf(ar[i], br[j], acc[i][j]);
        }
        __syncthreads();
    }

    float bv[8];
#pragma unroll
    for (int j = 0; j < 8; j++)
        bv[j] = bias ? bias[col0 + tc + j] : 0.0f;

#pragma unroll
    for (int i = 0; i < 8; i++) {
        int r = row0 + tr + i;
        if (r >= M) continue;
        float* cp = C + (size_t)r * N + col0 + tc;
#pragma unroll
        for (int j = 0; j < 8; j += 4) {
            float4 v;
            v.x = acc[i][j + 0] + bv[j + 0];
            v.y = acc[i][j + 1] + bv[j + 1];
            v.z = acc[i][j + 2] + bv[j + 2];
            v.w = acc[i][j + 3] + bv[j + 3];
            *(float4*)(cp + j) = v;
        }
    }
}

// ------------------------------------------------------------------
// z[n, r*256+j] = sum_b comp[r,b] * xb[n, b*256+j]
// ------------------------------------------------------------------
__global__ void combine_k(const float* __restrict__ comp) {
    int idx = blockIdx.x * blockDim.x + threadIdx.x;  // over N_NODES*64
    if (idx >= N_NODES * 64) return;
    int n  = idx >> 6;
    int j4 = (idx & 63);   // float4 index within 256-float row
    const float4* xb = (const float4*)(g_xb + (size_t)n * (B_BAS * D_H));
    float4 xv[B_BAS];
#pragma unroll
    for (int b = 0; b < B_BAS; b++) xv[b] = xb[b * 64 + j4];
    float4* zp = (float4*)(g_z + (size_t)n * (R_REL * D_H));
#pragma unroll
    for (int r = 0; r < R_REL; r++) {
        float c0 = comp[r * B_BAS + 0];
        float c1 = comp[r * B_BAS + 1];
        float c2 = comp[r * B_BAS + 2];
        float c3 = comp[r * B_BAS + 3];
        float4 o;
        o.x = c0 * xv[0].x + c1 * xv[1].x + c2 * xv[2].x + c3 * xv[3].x;
        o.y = c0 * xv[0].y + c1 * xv[1].y + c2 * xv[2].y + c3 * xv[3].y;
        o.z = c0 * xv[0].z + c1 * xv[1].z + c2 * xv[2].z + c3 * xv[3].z;
        o.w = c0 * xv[0].w + c1 * xv[1].w + c2 * xv[2].w + c3 * xv[3].w;
        zp[r * 64 + j4] = o;
    }
}

// ------------------------------------------------------------------
// Edge aggregation: one warp per edge.
// (useH ? g_h : outExt)[dst] += norm[dst,rel] * z[src, rel, :]
// ------------------------------------------------------------------
__global__ void edge_k(const int* __restrict__ ei,
                       const int* __restrict__ et,
                       float* __restrict__ outExt, int useH) {
    int gt = blockIdx.x * blockDim.x + threadIdx.x;
    int e = gt >> 5;
    int lane = gt & 31;
    if (e >= E_EDGES) return;
    float* out = useH ? (float*)g_h : outExt;
    int src = ei[e];
    int dst = ei[E_EDGES + e];
    int r   = et[e];
    float w = g_norm[dst * R_REL + r];
    const float4* zp = (const float4*)(g_z + (size_t)src * (R_REL * D_H) + r * D_H);
    float* op = out + (size_t)dst * D_H;
#pragma unroll
    for (int half = 0; half < 2; half++) {
        int j = lane + half * 32;            // float4 index 0..63
        float4 v = zp[j];
        float* addr = op + j * 4;
        atomicAdd(addr + 0, v.x * w);
        atomicAdd(addr + 1, v.y * w);
        atomicAdd(addr + 2, v.z * w);
        atomicAdd(addr + 3, v.w * w);
    }
}

__global__ void relu_k() {
    int i = blockIdx.x * blockDim.x + threadIdx.x;
    if (i < N_NODES * D_H) g_h[i] = fmaxf(g_h[i], 0.0f);
}

// ------------------------------------------------------------------
extern "C" void kernel_launch(void* const* d_in, const int* in_sizes, int n_in,
                              void* d_out, int out_size) {
    const float* x      = (const float*)d_in[0];
    const int*   ei     = (const int*)d_in[1];
    const int*   et     = (const int*)d_in[2];
    const float* basis1 = (const float*)d_in[3];
    const float* comp1  = (const float*)d_in[4];
    const float* root1  = (const float*)d_in[5];
    const float* bias1  = (const float*)d_in[6];
    const float* basis2 = (const float*)d_in[7];
    const float* comp2  = (const float*)d_in[8];
    const float* root2  = (const float*)d_in[9];
    const float* bias2  = (const float*)d_in[10];
    float* out = (float*)d_out;

    const int T = 256;

    // graph-structure prep (shared by both layers)
    zero_cnt_k<<<(N_NODES * R_REL + T - 1) / T, T>>>();
    count_k<<<(E_EDGES + T - 1) / T, T>>>(ei, et);
    norm_k<<<(N_NODES * R_REL + T - 1) / T, T>>>();

    dim3 gXB(B_BAS * D_H / 128, (N_NODES + 127) / 128);   // N=1024 cols
    dim3 gRT(D_H / 128, (N_NODES + 127) / 128);           // N=256 cols
    int edgeBlocks = (E_EDGES * 32 + T - 1) / T;

    // ---------------- layer 1 ----------------
    trans_basis_k<<<(D_IN * B_BAS * D_H + T - 1) / T, T>>>(basis1);
    // xb = x @ w
    sgemm128_k<<<gXB, T>>>(x, 0, nullptr, 1, nullptr, 1, N_NODES, B_BAS * D_H, nullptr);
    combine_k<<<(N_NODES * 64 + T - 1) / T, T>>>(comp1);
    // h = x @ root1 + bias1
    sgemm128_k<<<gRT, T>>>(x, 0, root1, 0, nullptr, 2, N_NODES, D_H, bias1);
    edge_k<<<edgeBlocks, T>>>(ei, et, nullptr, 1);
    relu_k<<<(N_NODES * D_H + T - 1) / T, T>>>();

    // ---------------- layer 2 ----------------
    trans_basis_k<<<(D_IN * B_BAS * D_H + T - 1) / T, T>>>(basis2);
    // xb = h @ w
    sgemm128_k<<<gXB, T>>>(nullptr, 1, nullptr, 1, nullptr, 1, N_NODES, B_BAS * D_H, nullptr);
    combine_k<<<(N_NODES * 64 + T - 1) / T, T>>>(comp2);
    // out = h @ root2 + bias2
    sgemm128_k<<<gRT, T>>>(nullptr, 1, root2, 0, out, 0, N_NODES, D_H, bias2);
    edge_k<<<edgeBlocks, T>>>(ei, et, out, 0);
}

// round 6
// speedup vs baseline: 2.6752x; 2.6752x over previous
#include <cuda_runtime.h>
#include <cuda_bf16.h>
#include <cstdint>

#define N_NODES 50000
#define E_EDGES 800000
#define D       256
#define R_REL   8
#define B_BAS   4
#define KTOT    1280          // 4*256 (t) + 256 (features)
#define KPAIR   640           // bf16 pairs per W column row

// ------------------------------------------------------------------
// Scratch (device globals; referenced only from device code)
// ------------------------------------------------------------------
__device__ __align__(16) float    g_a1[(size_t)N_NODES * KTOT];   // [t1 | x]    256 MB
__device__ __align__(16) float    g_a2[(size_t)N_NODES * KTOT];   // [t2 | h]    256 MB
__device__ __align__(16) uint32_t g_wbh[(size_t)D * KPAIR];       // W hi, n-major, k-pairs
__device__ __align__(16) uint32_t g_wbl[(size_t)D * KPAIR];       // W lo
__device__ __align__(16) float    g_norm[N_NODES * R_REL];
__device__ __align__(16) int      g_cnt [N_NODES * R_REL];
__device__ __align__(16) int      g_deg [N_NODES];
__device__ __align__(16) int      g_rowptr[N_NODES + 1];
__device__ __align__(16) int      g_wcur[N_NODES];
__device__ __align__(16) int      g_epack[E_EDGES];

// ------------------------------------------------------------------
// Graph prep
// ------------------------------------------------------------------
__global__ void zero_cnt_k() {
    int i = blockIdx.x * blockDim.x + threadIdx.x;
    if (i < N_NODES * R_REL) g_cnt[i] = 0;
}

__global__ void count_k(const int* __restrict__ ei, const int* __restrict__ et) {
    int e = blockIdx.x * blockDim.x + threadIdx.x;
    if (e >= E_EDGES) return;
    atomicAdd(&g_cnt[ei[E_EDGES + e] * R_REL + et[e]], 1);
}

__global__ void norm_deg_k() {
    int i = blockIdx.x * blockDim.x + threadIdx.x;
    if (i >= N_NODES) return;
    int deg = 0;
#pragma unroll
    for (int r = 0; r < R_REL; r++) {
        int c = g_cnt[i * R_REL + r];
        g_norm[i * R_REL + r] = 1.0f / (float)(c > 0 ? c : 1);
        deg += c;
    }
    g_deg[i] = deg;
}

// single-block exclusive scan over g_deg -> g_rowptr / g_wcur
__global__ void scan_k() {
    __shared__ int sums[1024];
    const int CH = (N_NODES + 1023) / 1024;   // 49
    int tid = threadIdx.x;
    int base = tid * CH;
    int s = 0;
    for (int i = 0; i < CH; i++) {
        int idx = base + i;
        if (idx < N_NODES) s += g_deg[idx];
    }
    sums[tid] = s;
    __syncthreads();
    for (int off = 1; off < 1024; off <<= 1) {
        int v = (tid >= off) ? sums[tid - off] : 0;
        __syncthreads();
        sums[tid] += v;
        __syncthreads();
    }
    int run = (tid == 0) ? 0 : sums[tid - 1];
    for (int i = 0; i < CH; i++) {
        int idx = base + i;
        if (idx < N_NODES) {
            g_rowptr[idx] = run;
            g_wcur[idx]   = run;
            run += g_deg[idx];
        }
    }
    if (tid == 1023) g_rowptr[N_NODES] = run;
}

__global__ void scatter_k(const int* __restrict__ ei, const int* __restrict__ et) {
    int e = blockIdx.x * blockDim.x + threadIdx.x;
    if (e >= E_EDGES) return;
    int src = ei[e];
    int dst = ei[E_EDGES + e];
    int r   = et[e];
    int pos = atomicAdd(&g_wcur[dst], 1);
    g_epack[pos] = src | (r << 16);          // N_NODES < 65536
}

// copy x into feature region of g_a1 (cols 1024..1279)
__global__ void copy_feat_k(const float* __restrict__ x) {
    int id = blockIdx.x * blockDim.x + threadIdx.x;   // over N*64 float4s
    if (id >= N_NODES * 64) return;
    int row = id >> 6, j4 = id & 63;
    float4 v = ((const float4*)(x + (size_t)row * D))[j4];
    *(float4*)(g_a1 + (size_t)row * KTOT + 1024 + j4 * 4) = v;
}

// ------------------------------------------------------------------
// Weight prep: W[1280][256] = [basis_flat ; root] split into bf16
// hi/lo, stored n-major with k-pairs: g_wb*[n*640 + kk]
// ------------------------------------------------------------------
__global__ void prep_w_k(const float* __restrict__ basis,
                         const float* __restrict__ root) {
    int id = blockIdx.x * blockDim.x + threadIdx.x;   // over 256*640
    if (id >= D * KPAIR) return;
    int n = id / KPAIR, kk = id % KPAIR;
    int k0 = kk * 2;
    float x0 = (k0 < 1024) ? basis[(size_t)k0 * D + n]
                           : root[(size_t)(k0 - 1024) * D + n];
    float x1 = (k0 + 1 < 1024) ? basis[(size_t)(k0 + 1) * D + n]
                               : root[(size_t)(k0 + 1 - 1024) * D + n];
    __nv_bfloat162 h = __floats2bfloat162_rn(x0, x1);
    float l0 = x0 - __bfloat162float(h.x);
    float l1 = x1 - __bfloat162float(h.y);
    __nv_bfloat162 l = __floats2bfloat162_rn(l0, l1);
    g_wbh[id] = *(uint32_t*)&h;
    g_wbl[id] = *(uint32_t*)&l;
}

// ------------------------------------------------------------------
// CSR edge aggregation: one warp per dst node.
// t[dst, b*256 + c] = sum_edges comp[r,b]*norm[dst,r]*feat[src, c]
// feat region = a[.. + 1024..1279]; t region = a[.. + 0..1023]
// ------------------------------------------------------------------
__global__ __launch_bounds__(256)
void edge_agg_k(const float* __restrict__ comp, int sel) {
    float* a = sel ? g_a2 : g_a1;
    __shared__ float comp_s[R_REL * B_BAS];
    if (threadIdx.x < R_REL * B_BAS) comp_s[threadIdx.x] = comp[threadIdx.x];
    __syncthreads();

    int dst  = (blockIdx.x * 256 + threadIdx.x) >> 5;   // grid sized exactly
    int lane = threadIdx.x & 31;
    if (dst >= N_NODES) return;

    int e0 = g_rowptr[dst], e1 = g_rowptr[dst + 1];
    float acc[B_BAS][8];
#pragma unroll
    for (int b = 0; b < B_BAS; b++)
#pragma unroll
        for (int k = 0; k < 8; k++) acc[b][k] = 0.0f;

    const float* featbase = a + 1024 + lane * 8;
    for (int e = e0; e < e1; e++) {
        int p = g_epack[e];
        int src = p & 0xFFFF;
        int r   = p >> 16;
        float w = g_norm[dst * R_REL + r];
        const float4* fp = (const float4*)(featbase + (size_t)src * KTOT);
        float4 v0 = fp[0], v1 = fp[1];
#pragma unroll
        for (int b = 0; b < B_BAS; b++) {
            float c = comp_s[r * B_BAS + b] * w;
            acc[b][0] += c * v0.x; acc[b][1] += c * v0.y;
            acc[b][2] += c * v0.z; acc[b][3] += c * v0.w;
            acc[b][4] += c * v1.x; acc[b][5] += c * v1.y;
            acc[b][6] += c * v1.z; acc[b][7] += c * v1.w;
        }
    }

    float* tp = a + (size_t)dst * KTOT + lane * 8;
#pragma unroll
    for (int b = 0; b < B_BAS; b++) {
        *(float4*)(tp + b * D)     = make_float4(acc[b][0], acc[b][1], acc[b][2], acc[b][3]);
        *(float4*)(tp + b * D + 4) = make_float4(acc[b][4], acc[b][5], acc[b][6], acc[b][7]);
    }
}

// ------------------------------------------------------------------
// bf16 3-term GEMM: C[M,256] = A[M,1280] @ W + bias (optional relu)
// mma.sync.m16n8k16, CTA tile 128x128, warp tile 32x64, K chunks of 32.
// ------------------------------------------------------------------
__device__ __forceinline__ void mma_bf16(float* c, uint32_t a0, uint32_t a1,
                                         uint32_t a2, uint32_t a3,
                                         uint32_t b0, uint32_t b1) {
    asm volatile(
        "mma.sync.aligned.m16n8k16.row.col.f32.bf16.bf16.f32 "
        "{%0,%1,%2,%3}, {%4,%5,%6,%7}, {%8,%9}, {%0,%1,%2,%3};"
        : "+f"(c[0]), "+f"(c[1]), "+f"(c[2]), "+f"(c[3])
        : "r"(a0), "r"(a1), "r"(a2), "r"(a3), "r"(b0), "r"(b1));
}

#define SSTR 20   // smem row stride in uint32 (16 pairs + 4 pad) — bank-distinct

__global__ __launch_bounds__(256, 2)
void gemm_k(int aSel, float* __restrict__ outExt, int mode,
            const float* __restrict__ bias, int M) {
    __shared__ uint32_t Ah[128 * SSTR], Al[128 * SSTR];
    __shared__ uint32_t Bh[128 * SSTR], Bl[128 * SSTR];

    const float* A = aSel ? g_a2 : g_a1;
    int tid  = threadIdx.x;
    int wid  = tid >> 5, lane = tid & 31;
    int gq   = lane >> 2, t4 = lane & 3;
    int warp_m = wid & 3, warp_n = wid >> 2;
    int row0 = blockIdx.y * 128, c0 = blockIdx.x * 128;

    float acc[2][8][4];
#pragma unroll
    for (int mb = 0; mb < 2; mb++)
#pragma unroll
        for (int nb = 0; nb < 8; nb++)
#pragma unroll
            for (int c = 0; c < 4; c++) acc[mb][nb][c] = 0.0f;

    for (int kc = 0; kc < KTOT / 32; kc++) {
        // ---- A: 128 rows x 32 k, fp32 -> bf16 hi/lo pairs ----
#pragma unroll
        for (int f = 0; f < 4; f++) {
            int id = tid + f * 256;
            int row = id >> 3, kf4 = id & 7;
            int gr = row0 + row;
            float4 v = make_float4(0.f, 0.f, 0.f, 0.f);
            if (gr < M)
                v = *(const float4*)(A + (size_t)gr * KTOT + kc * 32 + kf4 * 4);
            __nv_bfloat162 h0 = __floats2bfloat162_rn(v.x, v.y);
            __nv_bfloat162 h1 = __floats2bfloat162_rn(v.z, v.w);
            float l0 = v.x - __bfloat162float(h0.x);
            float l1 = v.y - __bfloat162float(h0.y);
            float l2 = v.z - __bfloat162float(h1.x);
            float l3 = v.w - __bfloat162float(h1.y);
            __nv_bfloat162 q0 = __floats2bfloat162_rn(l0, l1);
            __nv_bfloat162 q1 = __floats2bfloat162_rn(l2, l3);
            *(uint2*)&Ah[row * SSTR + kf4 * 2] = make_uint2(*(uint32_t*)&h0, *(uint32_t*)&h1);
            *(uint2*)&Al[row * SSTR + kf4 * 2] = make_uint2(*(uint32_t*)&q0, *(uint32_t*)&q1);
        }
        // ---- B: 128 n-rows x 16 pairs (pre-split) ----
        {
            int n = tid >> 1, half = tid & 1;
            size_t gi = (size_t)(c0 + n) * KPAIR + kc * 16 + half * 8;
            uint4 u0 = *(const uint4*)(g_wbh + gi);
            uint4 u1 = *(const uint4*)(g_wbh + gi + 4);
            *(uint4*)&Bh[n * SSTR + half * 8]     = u0;
            *(uint4*)&Bh[n * SSTR + half * 8 + 4] = u1;
            u0 = *(const uint4*)(g_wbl + gi);
            u1 = *(const uint4*)(g_wbl + gi + 4);
            *(uint4*)&Bl[n * SSTR + half * 8]     = u0;
            *(uint4*)&Bl[n * SSTR + half * 8 + 4] = u1;
        }
        __syncthreads();

#pragma unroll
        for (int s = 0; s < 2; s++) {
            int kb = s * 8 + t4;
            uint32_t ah[2][4], al[2][4];
#pragma unroll
            for (int mb = 0; mb < 2; mb++) {
                int mr = warp_m * 32 + mb * 16 + gq;
                ah[mb][0] = Ah[mr * SSTR + kb];
                ah[mb][1] = Ah[(mr + 8) * SSTR + kb];
                ah[mb][2] = Ah[mr * SSTR + kb + 4];
                ah[mb][3] = Ah[(mr + 8) * SSTR + kb + 4];
                al[mb][0] = Al[mr * SSTR + kb];
                al[mb][1] = Al[(mr + 8) * SSTR + kb];
                al[mb][2] = Al[mr * SSTR + kb + 4];
                al[mb][3] = Al[(mr + 8) * SSTR + kb + 4];
            }
#pragma unroll
            for (int nb = 0; nb < 8; nb++) {
                int nr = warp_n * 64 + nb * 8 + gq;
                uint32_t bh0 = Bh[nr * SSTR + kb], bh1 = Bh[nr * SSTR + kb + 4];
                uint32_t bl0 = Bl[nr * SSTR + kb], bl1 = Bl[nr * SSTR + kb + 4];
#pragma unroll
                for (int mb = 0; mb < 2; mb++) {
                    mma_bf16(acc[mb][nb], ah[mb][0], ah[mb][1], ah[mb][2], ah[mb][3], bh0, bh1);
                    mma_bf16(acc[mb][nb], ah[mb][0], ah[mb][1], ah[mb][2], ah[mb][3], bl0, bl1);
                    mma_bf16(acc[mb][nb], al[mb][0], al[mb][1], al[mb][2], al[mb][3], bh0, bh1);
                }
            }
        }
        __syncthreads();
    }

    // ---- epilogue ----
#pragma unroll
    for (int nb = 0; nb < 8; nb++) {
        int coll = warp_n * 64 + nb * 8 + t4 * 2;
        float2 bv = *(const float2*)(bias + c0 + coll);
#pragma unroll
        for (int mb = 0; mb < 2; mb++) {
            int r0 = row0 + warp_m * 32 + mb * 16 + gq;
            int r1 = r0 + 8;
            float x0 = acc[mb][nb][0] + bv.x, x1 = acc[mb][nb][1] + bv.y;
            float x2 = acc[mb][nb][2] + bv.x, x3 = acc[mb][nb][3] + bv.y;
            if (mode == 1) {   // relu, write g_a2 feature region
                x0 = fmaxf(x0, 0.f); x1 = fmaxf(x1, 0.f);
                x2 = fmaxf(x2, 0.f); x3 = fmaxf(x3, 0.f);
                if (r0 < M) *(float2*)(g_a2 + (size_t)r0 * KTOT + 1024 + c0 + coll) = make_float2(x0, x1);
                if (r1 < M) *(float2*)(g_a2 + (size_t)r1 * KTOT + 1024 + c0 + coll) = make_float2(x2, x3);
            } else {           // external out [M,256]
                if (r0 < M) *(float2*)(outExt + (size_t)r0 * D + c0 + coll) = make_float2(x0, x1);
                if (r1 < M) *(float2*)(outExt + (size_t)r1 * D + c0 + coll) = make_float2(x2, x3);
            }
        }
    }
}

// ------------------------------------------------------------------
extern "C" void kernel_launch(void* const* d_in, const int* in_sizes, int n_in,
                              void* d_out, int out_size) {
    const float* x      = (const float*)d_in[0];
    const int*   ei     = (const int*)d_in[1];
    const int*   et     = (const int*)d_in[2];
    const float* basis1 = (const float*)d_in[3];
    const float* comp1  = (const float*)d_in[4];
    const float* root1  = (const float*)d_in[5];
    const float* bias1  = (const float*)d_in[6];
    const float* basis2 = (const float*)d_in[7];
    const float* comp2  = (const float*)d_in[8];
    const float* root2  = (const float*)d_in[9];
    const float* bias2  = (const float*)d_in[10];
    float* out = (float*)d_out;

    const int T = 256;

    // graph prep (once)
    zero_cnt_k<<<(N_NODES * R_REL + T - 1) / T, T>>>();
    count_k<<<(E_EDGES + T - 1) / T, T>>>(ei, et);
    norm_deg_k<<<(N_NODES + T - 1) / T, T>>>();
    scan_k<<<1, 1024>>>();
    scatter_k<<<(E_EDGES + T - 1) / T, T>>>(ei, et);
    copy_feat_k<<<(N_NODES * 64 + T - 1) / T, T>>>(x);

    dim3 gG(2, (N_NODES + 127) / 128);                  // (2, 391)
    int aggBlocks = (N_NODES * 32 + T - 1) / T;          // 6250
    int wBlocks   = (D * KPAIR + T - 1) / T;

    // ---------------- layer 1 ----------------
    prep_w_k<<<wBlocks, T>>>(basis1, root1);
    edge_agg_k<<<aggBlocks, T>>>(comp1, 0);
    gemm_k<<<gG, T>>>(0, nullptr, 1, bias1, N_NODES);    // -> g_a2 features (relu)

    // ---------------- layer 2 ----------------
    prep_w_k<<<wBlocks, T>>>(basis2, root2);
    edge_agg_k<<<aggBlocks, T>>>(comp2, 1);
    gemm_k<<<gG, T>>>(1, out, 0, bias2, N_NODES);        // -> out
}

// round 7
// speedup vs baseline: 2.9945x; 1.1193x over previous
#include <cuda_runtime.h>
#include <cuda_bf16.h>
#include <cstdint>

#define N_NODES 50000
#define NPAD    50176         // 196*256, padded rows for unguarded tile loads
#define E_EDGES 800000
#define D       256
#define R_REL   8
#define B_BAS   4
#define KTOT    1280          // 4*256 (t) + 256 (features)
#define KPAIR   640           // bf16 pairs per A/W row
#define SCB     196           // scan blocks

// ------------------------------------------------------------------
// Scratch (device globals; referenced only from device code)
// A stored pre-split: hi/lo bf16 pairs, row-major [node][kpair]
// ------------------------------------------------------------------
__device__ __align__(16) uint32_t g_ah1[(size_t)NPAD * KPAIR];
__device__ __align__(16) uint32_t g_al1[(size_t)NPAD * KPAIR];
__device__ __align__(16) uint32_t g_ah2[(size_t)NPAD * KPAIR];
__device__ __align__(16) uint32_t g_al2[(size_t)NPAD * KPAIR];
__device__ __align__(16) uint32_t g_wbh[(size_t)D * KPAIR];
__device__ __align__(16) uint32_t g_wbl[(size_t)D * KPAIR];
__device__ __align__(16) float    g_norm[N_NODES * R_REL];
__device__ __align__(16) int      g_cnt [N_NODES * R_REL];
__device__ __align__(16) int      g_deg [N_NODES];
__device__ __align__(16) int      g_part[256];
__device__ __align__(16) int      g_rowptr[N_NODES + 1];
__device__ __align__(16) int      g_wcur[N_NODES];
__device__ __align__(16) int      g_epack[E_EDGES];

// ------------------------------------------------------------------
// helpers
// ------------------------------------------------------------------
__device__ __forceinline__ uint32_t smem_u32(const void* p) {
    uint32_t a;
    asm("{ .reg .u64 t; cvta.to.shared.u64 t, %1; cvt.u32.u64 %0, t; }"
        : "=r"(a) : "l"(p));
    return a;
}

__device__ __forceinline__ void split2(float a, float b, uint32_t& h, uint32_t& l) {
    __nv_bfloat162 hh = __floats2bfloat162_rn(a, b);
    float la = a - __bfloat162float(hh.x);
    float lb = b - __bfloat162float(hh.y);
    __nv_bfloat162 ll = __floats2bfloat162_rn(la, lb);
    h = *(uint32_t*)&hh;
    l = *(uint32_t*)&ll;
}

__device__ __forceinline__ float2 upk2(uint32_t h, uint32_t l) {
    float2 a = __bfloat1622float2(*(__nv_bfloat162*)&h);
    float2 b = __bfloat1622float2(*(__nv_bfloat162*)&l);
    return make_float2(a.x + b.x, a.y + b.y);
}

__device__ __forceinline__ void cp16(uint32_t dst, const void* src) {
    asm volatile("cp.async.cg.shared.global [%0], [%1], 16;" :: "r"(dst), "l"(src));
}

__device__ __forceinline__ void ldsm_x4(uint32_t* r, uint32_t a) {
    asm volatile("ldmatrix.sync.aligned.m8n8.x4.shared.b16 {%0,%1,%2,%3}, [%4];"
        : "=r"(r[0]), "=r"(r[1]), "=r"(r[2]), "=r"(r[3]) : "r"(a));
}

__device__ __forceinline__ void ldsm_x2(uint32_t& r0, uint32_t& r1, uint32_t a) {
    asm volatile("ldmatrix.sync.aligned.m8n8.x2.shared.b16 {%0,%1}, [%2];"
        : "=r"(r0), "=r"(r1) : "r"(a));
}

__device__ __forceinline__ void mma_bf16(float* c, const uint32_t* a,
                                         uint32_t b0, uint32_t b1) {
    asm volatile(
        "mma.sync.aligned.m16n8k16.row.col.f32.bf16.bf16.f32 "
        "{%0,%1,%2,%3}, {%4,%5,%6,%7}, {%8,%9}, {%0,%1,%2,%3};"
        : "+f"(c[0]), "+f"(c[1]), "+f"(c[2]), "+f"(c[3])
        : "r"(a[0]), "r"(a[1]), "r"(a[2]), "r"(a[3]), "r"(b0), "r"(b1));
}

// ------------------------------------------------------------------
// Graph prep
// ------------------------------------------------------------------
__global__ void zero_cnt_k() {
    int i = blockIdx.x * blockDim.x + threadIdx.x;
    if (i < N_NODES * R_REL) g_cnt[i] = 0;
}

__global__ void count_k(const int* __restrict__ ei, const int* __restrict__ et) {
    int e = blockIdx.x * blockDim.x + threadIdx.x;
    if (e >= E_EDGES) return;
    atomicAdd(&g_cnt[ei[E_EDGES + e] * R_REL + et[e]], 1);
}

__global__ void norm_deg_k() {
    int i = blockIdx.x * blockDim.x + threadIdx.x;
    if (i >= N_NODES) return;
    int deg = 0;
#pragma unroll
    for (int r = 0; r < R_REL; r++) {
        int c = g_cnt[i * R_REL + r];
        g_norm[i * R_REL + r] = 1.0f / (float)(c > 0 ? c : 1);
        deg += c;
    }
    g_deg[i] = deg;
}

// multi-block exclusive scan: partial sums -> scan partials -> rowptr
__global__ void partial_k() {
    __shared__ int s[256];
    int b = blockIdx.x, t = threadIdx.x, i = b * 256 + t;
    s[t] = (i < N_NODES) ? g_deg[i] : 0;
    __syncthreads();
    for (int o = 128; o > 0; o >>= 1) {
        if (t < o) s[t] += s[t + o];
        __syncthreads();
    }
    if (t == 0) g_part[b] = s[0];
}

__global__ void scanp_k() {
    __shared__ int s[256];
    int t = threadIdx.x;
    s[t] = (t < SCB) ? g_part[t] : 0;
    __syncthreads();
    for (int o = 1; o < 256; o <<= 1) {
        int v = (t >= o) ? s[t - o] : 0;
        __syncthreads();
        s[t] += v;
        __syncthreads();
    }
    g_part[t] = (t == 0) ? 0 : s[t - 1];
}

__global__ void rowptr_k() {
    __shared__ int s[256];
    int b = blockIdx.x, t = threadIdx.x, i = b * 256 + t;
    int d = (i < N_NODES) ? g_deg[i] : 0;
    s[t] = d;
    __syncthreads();
    for (int o = 1; o < 256; o <<= 1) {
        int v = (t >= o) ? s[t - o] : 0;
        __syncthreads();
        s[t] += v;
        __syncthreads();
    }
    int excl = g_part[b] + s[t] - d;
    if (i < N_NODES) { g_rowptr[i] = excl; g_wcur[i] = excl; }
    if (i == N_NODES - 1) g_rowptr[N_NODES] = excl + d;
}

__global__ void scatter_k(const int* __restrict__ ei, const int* __restrict__ et) {
    int e = blockIdx.x * blockDim.x + threadIdx.x;
    if (e >= E_EDGES) return;
    int src = ei[e];
    int dst = ei[E_EDGES + e];
    int r   = et[e];
    int pos = atomicAdd(&g_wcur[dst], 1);
    g_epack[pos] = src | (r << 16);          // N_NODES < 65536
}

// x -> split bf16 feature region of A1 (pairs 512..639)
__global__ void copy_feat_k(const float* __restrict__ x) {
    int id = blockIdx.x * blockDim.x + threadIdx.x;   // over N*128 pairs
    if (id >= N_NODES * 128) return;
    int row = id >> 7, p = id & 127;
    float2 v = *(const float2*)(x + (size_t)row * D + p * 2);
    uint32_t h, l;
    split2(v.x, v.y, h, l);
    g_ah1[(size_t)row * KPAIR + 512 + p] = h;
    g_al1[(size_t)row * KPAIR + 512 + p] = l;
}

// W[1280][256] = [basis_flat ; root] -> split bf16, n-major pairs
__global__ void prep_w_k(const float* __restrict__ basis,
                         const float* __restrict__ root) {
    int id = blockIdx.x * blockDim.x + threadIdx.x;   // over 256*640
    if (id >= D * KPAIR) return;
    int n = id / KPAIR, kk = id % KPAIR;
    int k0 = kk * 2;
    float x0 = (k0 < 1024) ? basis[(size_t)k0 * D + n]
                           : root[(size_t)(k0 - 1024) * D + n];
    float x1 = (k0 + 1 < 1024) ? basis[(size_t)(k0 + 1) * D + n]
                               : root[(size_t)(k0 + 1 - 1024) * D + n];
    uint32_t h, l;
    split2(x0, x1, h, l);
    g_wbh[id] = h;
    g_wbl[id] = l;
}

// ------------------------------------------------------------------
// CSR edge aggregation: one warp per dst.
// Reads split features (pairs 512+), writes split t (pairs 0..511).
// ------------------------------------------------------------------
__global__ __launch_bounds__(256)
void edge_agg_k(const float* __restrict__ comp, int sel) {
    uint32_t* gah = sel ? g_ah2 : g_ah1;
    uint32_t* gal = sel ? g_al2 : g_al1;
    __shared__ float comp_s[R_REL * B_BAS];
    if (threadIdx.x < R_REL * B_BAS) comp_s[threadIdx.x] = comp[threadIdx.x];
    __syncthreads();

    int dst  = (blockIdx.x * 256 + threadIdx.x) >> 5;
    int lane = threadIdx.x & 31;
    if (dst >= N_NODES) return;

    int e0 = g_rowptr[dst], e1 = g_rowptr[dst + 1];
    float acc[B_BAS][8];
#pragma unroll
    for (int b = 0; b < B_BAS; b++)
#pragma unroll
        for (int k = 0; k < 8; k++) acc[b][k] = 0.0f;

    for (int e = e0; e < e1; e++) {
        int p = g_epack[e];
        int src = p & 0xFFFF;
        int r   = p >> 16;
        float w = g_norm[dst * R_REL + r];
        size_t fo = (size_t)src * KPAIR + 512 + lane * 4;
        uint4 hq = *(const uint4*)(gah + fo);
        uint4 lq = *(const uint4*)(gal + fo);
        float2 v0 = upk2(hq.x, lq.x), v1 = upk2(hq.y, lq.y);
        float2 v2 = upk2(hq.z, lq.z), v3 = upk2(hq.w, lq.w);
#pragma unroll
        for (int b = 0; b < B_BAS; b++) {
            float c = comp_s[r * B_BAS + b] * w;
            acc[b][0] += c * v0.x; acc[b][1] += c * v0.y;
            acc[b][2] += c * v1.x; acc[b][3] += c * v1.y;
            acc[b][4] += c * v2.x; acc[b][5] += c * v2.y;
            acc[b][6] += c * v3.x; acc[b][7] += c * v3.y;
        }
    }

#pragma unroll
    for (int b = 0; b < B_BAS; b++) {
        uint4 hv, lv;
        split2(acc[b][0], acc[b][1], hv.x, lv.x);
        split2(acc[b][2], acc[b][3], hv.y, lv.y);
        split2(acc[b][4], acc[b][5], hv.z, lv.z);
        split2(acc[b][6], acc[b][7], hv.w, lv.w);
        size_t to = (size_t)dst * KPAIR + b * 128 + lane * 4;
        *(uint4*)(gah + to) = hv;
        *(uint4*)(gal + to) = lv;
    }
}

// ------------------------------------------------------------------
// bf16 3-term GEMM: C[M,256] = A[M,1280] @ W + bias (opt relu->split A2)
// cp.async 2-stage pipeline, ldmatrix fragments, mma m16n8k16.
// ------------------------------------------------------------------
#define SSTR 20                 // smem row stride (uint32): 16 pairs + 4 pad
#define ASZ  (128 * SSTR)       // one tile array (uint32 count)
#define GSMEM (8 * ASZ * 4)     // 2 bufs x 4 arrays = 81920 B

__global__ __launch_bounds__(256, 2)
void gemm_k(int aSel, float* __restrict__ outExt, int mode,
            const float* __restrict__ bias, int M) {
    extern __shared__ uint32_t smem[];
    uint32_t sb = smem_u32(smem);

    const uint32_t* gah = aSel ? g_ah2 : g_ah1;
    const uint32_t* gal = aSel ? g_al2 : g_al1;

    int tid  = threadIdx.x;
    int wid  = tid >> 5, lane = tid & 31;
    int gq   = lane >> 2, t4 = lane & 3;
    int warp_m = wid & 3, warp_n = wid >> 2;
    int row0 = blockIdx.y * 128, c0 = blockIdx.x * 128;

    // ldmatrix per-lane offsets
    int rA = (lane & 7) + ((lane >> 3) & 1) * 8;
    int qA = (lane >> 4) * 4;
    int rB = lane & 7;
    int hB = ((lane >> 3) & 1) * 4;

    float acc[2][8][4];
#pragma unroll
    for (int mb = 0; mb < 2; mb++)
#pragma unroll
        for (int nb = 0; nb < 8; nb++)
#pragma unroll
            for (int c = 0; c < 4; c++) acc[mb][nb][c] = 0.0f;

    // copy mapping: id in [0,512): row=id>>2, quad=id&3
    int cr = tid >> 2 << 1;            // rows 2*(tid>>2), +1 handled by f loop
    // (use straightforward 2-iteration mapping instead)

#define PREFETCH(kc, buf) do {                                                \
    int _kc = (kc), _b = (buf);                                               \
    uint32_t bA = sb + (uint32_t)((_b * 4 + 0) * ASZ) * 4;                    \
    uint32_t bAl = sb + (uint32_t)((_b * 4 + 1) * ASZ) * 4;                   \
    uint32_t bB = sb + (uint32_t)((_b * 4 + 2) * ASZ) * 4;                    \
    uint32_t bBl = sb + (uint32_t)((_b * 4 + 3) * ASZ) * 4;                   \
    _Pragma("unroll")                                                         \
    for (int f = 0; f < 2; f++) {                                             \
        int id = tid + f * 256;                                               \
        int row = id >> 2, q = id & 3;                                        \
        uint32_t doff = (uint32_t)(row * SSTR + q * 4) * 4;                   \
        size_t ga = (size_t)(row0 + row) * KPAIR + _kc * 16 + q * 4;          \
        cp16(bA + doff, gah + ga);                                            \
        cp16(bAl + doff, gal + ga);                                           \
        size_t gb = (size_t)(c0 + row) * KPAIR + _kc * 16 + q * 4;            \
        cp16(bB + doff, g_wbh + gb);                                          \
        cp16(bBl + doff, g_wbl + gb);                                         \
    }                                                                         \
} while (0)

    const int NC = KPAIR / 16;   // 40
    PREFETCH(0, 0);
    asm volatile("cp.async.commit_group;" ::: "memory");

    for (int kc = 0; kc < NC; kc++) {
        if (kc + 1 < NC) {
            PREFETCH(kc + 1, (kc + 1) & 1);
            asm volatile("cp.async.commit_group;" ::: "memory");
            asm volatile("cp.async.wait_group 1;" ::: "memory");
        } else {
            asm volatile("cp.async.wait_group 0;" ::: "memory");
        }
        __syncthreads();

        int buf = kc & 1;
        uint32_t bAH = sb + (uint32_t)((buf * 4 + 0) * ASZ) * 4;
        uint32_t bAL = sb + (uint32_t)((buf * 4 + 1) * ASZ) * 4;
        uint32_t bBH = sb + (uint32_t)((buf * 4 + 2) * ASZ) * 4;
        uint32_t bBL = sb + (uint32_t)((buf * 4 + 3) * ASZ) * 4;

#pragma unroll
        for (int s = 0; s < 2; s++) {
            uint32_t ah[2][4], al[2][4];
#pragma unroll
            for (int mb = 0; mb < 2; mb++) {
                uint32_t off = (uint32_t)((warp_m * 32 + mb * 16 + rA) * SSTR
                                          + s * 8 + qA) * 4;
                ldsm_x4(ah[mb], bAH + off);
                ldsm_x4(al[mb], bAL + off);
            }
#pragma unroll
            for (int nb = 0; nb < 8; nb++) {
                uint32_t offb = (uint32_t)((warp_n * 64 + nb * 8 + rB) * SSTR
                                           + s * 8 + hB) * 4;
                uint32_t bh0, bh1, bl0, bl1;
                ldsm_x2(bh0, bh1, bBH + offb);
                ldsm_x2(bl0, bl1, bBL + offb);
#pragma unroll
                for (int mb = 0; mb < 2; mb++) {
                    mma_bf16(acc[mb][nb], ah[mb], bh0, bh1);
                    mma_bf16(acc[mb][nb], ah[mb], bl0, bl1);
                    mma_bf16(acc[mb][nb], al[mb], bh0, bh1);
                }
            }
        }
        __syncthreads();
    }

    // ---- epilogue ----
#pragma unroll
    for (int nb = 0; nb < 8; nb++) {
        int coll = warp_n * 64 + nb * 8 + t4 * 2;
        float2 bv = *(const float2*)(bias + c0 + coll);
#pragma unroll
        for (int mb = 0; mb < 2; mb++) {
            int r0 = row0 + warp_m * 32 + mb * 16 + gq;
            int r1 = r0 + 8;
            float x0 = acc[mb][nb][0] + bv.x, x1 = acc[mb][nb][1] + bv.y;
            float x2 = acc[mb][nb][2] + bv.x, x3 = acc[mb][nb][3] + bv.y;
            if (mode == 1) {       // relu + split -> A2 feature region
                x0 = fmaxf(x0, 0.f); x1 = fmaxf(x1, 0.f);
                x2 = fmaxf(x2, 0.f); x3 = fmaxf(x3, 0.f);
                int p = (1024 + c0 + coll) >> 1;
                uint32_t h, l;
                if (r0 < M) {
                    split2(x0, x1, h, l);
                    g_ah2[(size_t)r0 * KPAIR + p] = h;
                    g_al2[(size_t)r0 * KPAIR + p] = l;
                }
                if (r1 < M) {
                    split2(x2, x3, h, l);
                    g_ah2[(size_t)r1 * KPAIR + p] = h;
                    g_al2[(size_t)r1 * KPAIR + p] = l;
                }
            } else {
                if (r0 < M) *(float2*)(outExt + (size_t)r0 * D + c0 + coll) = make_float2(x0, x1);
                if (r1 < M) *(float2*)(outExt + (size_t)r1 * D + c0 + coll) = make_float2(x2, x3);
            }
        }
    }
}

// ------------------------------------------------------------------
extern "C" void kernel_launch(void* const* d_in, const int* in_sizes, int n_in,
                              void* d_out, int out_size) {
    const float* x      = (const float*)d_in[0];
    const int*   ei     = (const int*)d_in[1];
    const int*   et     = (const int*)d_in[2];
    const float* basis1 = (const float*)d_in[3];
    const float* comp1  = (const float*)d_in[4];
    const float* root1  = (const float*)d_in[5];
    const float* bias1  = (const float*)d_in[6];
    const float* basis2 = (const float*)d_in[7];
    const float* comp2  = (const float*)d_in[8];
    const float* root2  = (const float*)d_in[9];
    const float* bias2  = (const float*)d_in[10];
    float* out = (float*)d_out;

    cudaFuncSetAttribute(gemm_k, cudaFuncAttributeMaxDynamicSharedMemorySize, GSMEM);

    const int T = 256;

    // graph prep (once per launch)
    zero_cnt_k<<<(N_NODES * R_REL + T - 1) / T, T>>>();
    count_k<<<(E_EDGES + T - 1) / T, T>>>(ei, et);
    norm_deg_k<<<(N_NODES + T - 1) / T, T>>>();
    partial_k<<<SCB, 256>>>();
    scanp_k<<<1, 256>>>();
    rowptr_k<<<SCB, 256>>>();
    scatter_k<<<(E_EDGES + T - 1) / T, T>>>(ei, et);
    copy_feat_k<<<(N_NODES * 128 + T - 1) / T, T>>>(x);

    dim3 gG(2, (N_NODES + 127) / 128);                  // (2, 391)
    int aggBlocks = (N_NODES * 32 + T - 1) / T;          // 6250
    int wBlocks   = (D * KPAIR + T - 1) / T;

    // ---------------- layer 1 ----------------
    prep_w_k<<<wBlocks, T>>>(basis1, root1);
    edge_agg_k<<<aggBlocks, T>>>(comp1, 0);
    gemm_k<<<gG, T, GSMEM>>>(0, nullptr, 1, bias1, N_NODES);   // -> split h in A2

    // ---------------- layer 2 ----------------
    prep_w_k<<<wBlocks, T>>>(basis2, root2);
    edge_agg_k<<<aggBlocks, T>>>(comp2, 1);
    gemm_k<<<gG, T, GSMEM>>>(1, out, 0, bias2, N_NODES);       // -> out
}